// round 9
// baseline (speedup 1.0000x reference)
#include <cuda_runtime.h>
#include <cuda_bf16.h>

#define NN 100000
#define DD 64
#define EMAX 1000000
#define SCAN_CHUNK 512   // blocks = ceil(NN/512) = 196 <= 256

typedef unsigned long long u64;

// ---------------- f32x2 packed math (Blackwell sm_103a) ----------------
__device__ __forceinline__ u64 fma2(u64 a, u64 b, u64 c) {
    u64 d;
    asm("fma.rn.f32x2 %0, %1, %2, %3;" : "=l"(d) : "l"(a), "l"(b), "l"(c));
    return d;
}
__device__ __forceinline__ u64 add2(u64 a, u64 b) {
    u64 d;
    asm("add.rn.f32x2 %0, %1, %2;" : "=l"(d) : "l"(a), "l"(b));
    return d;
}
__device__ __forceinline__ u64 mul2(u64 a, u64 b) {
    u64 d;
    asm("mul.rn.f32x2 %0, %1, %2;" : "=l"(d) : "l"(a), "l"(b));
    return d;
}
__device__ __forceinline__ float lo32(u64 a) { return __uint_as_float((unsigned)a); }
__device__ __forceinline__ float hi32(u64 a) { return __uint_as_float((unsigned)(a >> 32)); }

// ---------------- device scratch (no allocation allowed) ----------------
__device__ float g_h0[NN * DD];
__device__ float g_h1[NN * DD];
__device__ float g_agg[NN * DD];
__device__ int   g_deg[NN];
__device__ int   g_rowptr[NN + 1];
__device__ int   g_cursor[NN];
__device__ int   g_col[EMAX];
__device__ u64   g_scan_state[256];   // memset to 0 each launch

// ---------------- CSR build ----------------
__global__ void k_hist(const int* __restrict__ dst, int* __restrict__ deg, int E) {
    for (int e = blockIdx.x * blockDim.x + threadIdx.x; e < E; e += gridDim.x * blockDim.x)
        atomicAdd(&deg[dst[e]], 1);
}

// single-pass decoupled-lookback exclusive scan: deg -> rowptr/cursor
__global__ void k_scan(const int* __restrict__ deg, int* __restrict__ rowptr,
                       int* __restrict__ cursor, u64* __restrict__ state,
                       int n, int nblk) {
    __shared__ int ps[256];
    __shared__ int s_ex;
    int b = blockIdx.x;
    int t = threadIdx.x;
    int base = b * SCAN_CHUNK + t * 2;
    int d0 = (base < n) ? deg[base] : 0;
    int d1 = (base + 1 < n) ? deg[base + 1] : 0;
    ps[t] = d0 + d1;
    __syncthreads();
    for (int d = 1; d < 256; d <<= 1) {
        int v = (t >= d) ? ps[t - d] : 0;
        __syncthreads();
        ps[t] += v;
        __syncthreads();
    }
    int total = ps[255];

    if (t == 0) {
        if (b == 0) {
            atomicExch(&state[0], ((u64)total << 2) | 2ULL);
            s_ex = 0;
        } else {
            atomicExch(&state[b], ((u64)total << 2) | 1ULL);
            int ex = 0;
            int p = b - 1;
            while (true) {
                u64 s;
                do {
                    s = *(volatile u64*)&state[p];
                } while ((s & 3ULL) == 0ULL);
                int v = (int)(s >> 2);
                ex += v;
                if ((s & 3ULL) == 2ULL) break;
                p--;
            }
            atomicExch(&state[b], ((u64)(ex + total) << 2) | 2ULL);
            s_ex = ex;
        }
    }
    __syncthreads();
    int off = s_ex + ps[t] - (d0 + d1);
    if (base < n)     { rowptr[base] = off;          cursor[base] = off; }
    if (base + 1 < n) { rowptr[base + 1] = off + d0; cursor[base + 1] = off + d0; }
    if (b == nblk - 1 && t == 255) rowptr[n] = s_ex + total;
}

__global__ void k_scatter(const int* __restrict__ src, const int* __restrict__ dst,
                          int* __restrict__ cursor, int* __restrict__ col, int E) {
    for (int e = blockIdx.x * blockDim.x + threadIdx.x; e < E; e += gridDim.x * blockDim.x) {
        int d = dst[e];
        int p = atomicAdd(&cursor[d], 1);
        col[p] = src[e];
    }
}

// ---------------- mean aggregation over node range [lo,hi) ----------------
__global__ __launch_bounds__(256) void k_agg(
    const float* __restrict__ h, const int* __restrict__ rowptr,
    const int* __restrict__ col, float* __restrict__ agg, int lo, int hi) {
    int node = lo + ((blockIdx.x * blockDim.x + threadIdx.x) >> 4);
    int l = threadIdx.x & 15;
    if (node >= hi) return;
    int s = rowptr[node];
    int e = rowptr[node + 1];
    u64 axy = 0ULL, azw = 0ULL;
    int nn = s;
    for (; nn + 8 <= e; nn += 8) {
        int c0 = col[nn],     c1 = col[nn + 1], c2 = col[nn + 2], c3 = col[nn + 3];
        int c4 = col[nn + 4], c5 = col[nn + 5], c6 = col[nn + 6], c7 = col[nn + 7];
        ulonglong2 v0 = ((const ulonglong2*)(h + c0 * DD))[l];
        ulonglong2 v1 = ((const ulonglong2*)(h + c1 * DD))[l];
        ulonglong2 v2 = ((const ulonglong2*)(h + c2 * DD))[l];
        ulonglong2 v3 = ((const ulonglong2*)(h + c3 * DD))[l];
        ulonglong2 v4 = ((const ulonglong2*)(h + c4 * DD))[l];
        ulonglong2 v5 = ((const ulonglong2*)(h + c5 * DD))[l];
        ulonglong2 v6 = ((const ulonglong2*)(h + c6 * DD))[l];
        ulonglong2 v7 = ((const ulonglong2*)(h + c7 * DD))[l];
        u64 p0 = add2(add2(v0.x, v1.x), add2(v2.x, v3.x));
        u64 p1 = add2(add2(v4.x, v5.x), add2(v6.x, v7.x));
        u64 q0 = add2(add2(v0.y, v1.y), add2(v2.y, v3.y));
        u64 q1 = add2(add2(v4.y, v5.y), add2(v6.y, v7.y));
        axy = add2(axy, add2(p0, p1));
        azw = add2(azw, add2(q0, q1));
    }
    for (; nn + 4 <= e; nn += 4) {
        int c0 = col[nn], c1 = col[nn + 1], c2 = col[nn + 2], c3 = col[nn + 3];
        ulonglong2 v0 = ((const ulonglong2*)(h + c0 * DD))[l];
        ulonglong2 v1 = ((const ulonglong2*)(h + c1 * DD))[l];
        ulonglong2 v2 = ((const ulonglong2*)(h + c2 * DD))[l];
        ulonglong2 v3 = ((const ulonglong2*)(h + c3 * DD))[l];
        axy = add2(axy, add2(add2(v0.x, v1.x), add2(v2.x, v3.x)));
        azw = add2(azw, add2(add2(v0.y, v1.y), add2(v2.y, v3.y)));
    }
    for (; nn < e; nn++) {
        ulonglong2 v = ((const ulonglong2*)(h + col[nn] * DD))[l];
        axy = add2(axy, v.x);
        azw = add2(azw, v.y);
    }
    float inv = (e > s) ? 1.f / (float)(e - s) : 0.f;
    unsigned ui = __float_as_uint(inv);
    u64 inv2 = ((u64)ui << 32) | ui;
    ((ulonglong2*)(agg + node * DD))[l] = make_ulonglong2(mul2(axy, inv2), mul2(azw, inv2));
}

// ---------------- node linear: out = x @ W^T + b (f32x2, double-buffered) ----------------
__global__ __launch_bounds__(256, 2) void k_lin(
    const float* __restrict__ x, const float* __restrict__ W,
    const float* __restrict__ b, float* __restrict__ out, int n) {
    __shared__ __align__(16) float sh[2][4][DD];
    int tid = threadIdx.x;
    int g = tid >> 6;
    int j = tid & 63;

    u64 w2[32];
#pragma unroll
    for (int k = 0; k < 32; k += 2) {
        ulonglong2 a = *(const ulonglong2*)&W[j * DD + k * 2];
        w2[k] = a.x;
        w2[k + 1] = a.y;
    }
    float bj = b[j];

    int stride = gridDim.x * 4;
    int i0 = blockIdx.x * 4 + g;
    float hv = (i0 < n) ? x[i0 * DD + j] : 0.f;
    int buf = 0;
    for (int base = blockIdx.x * 4; base < n; base += stride) {
        int i = base + g;
        sh[buf][g][j] = hv;
        __syncthreads();
        int inx = i + stride;
        hv = (inx < n) ? x[inx * DD + j] : 0.f;
        if (i < n) {
            const ulonglong2* h2 = (const ulonglong2*)sh[buf][g];
            u64 acc0 = 0ULL, acc1 = 0ULL;
#pragma unroll
            for (int k4 = 0; k4 < 16; k4++) {
                ulonglong2 H = h2[k4];
                acc0 = fma2(H.x, w2[2 * k4], acc0);
                acc1 = fma2(H.y, w2[2 * k4 + 1], acc1);
            }
            out[i * DD + j] = (lo32(acc0) + hi32(acc0)) + (lo32(acc1) + hi32(acc1)) + bj;
        }
        buf ^= 1;
    }
}

// ---------------- dense SAGE transform over [lo,hi): out = agg@Wl^T + bl + h@Wr^T ----------------
__global__ __launch_bounds__(256, 1) void k_gemm(
    const float* __restrict__ h, const float* __restrict__ agg,
    const float* __restrict__ Wl, const float* __restrict__ bl,
    const float* __restrict__ Wr, float* __restrict__ out,
    int lo, int hi, int do_relu) {
    __shared__ __align__(16) float sh[2][8][DD];
    __shared__ __align__(16) float sa[2][8][DD];
    int tid = threadIdx.x;
    int g = tid >> 6;       // 0..3
    int j = tid & 63;

    u64 wl2[32], wr2[32];
#pragma unroll
    for (int k = 0; k < 32; k += 2) {
        ulonglong2 a = *(const ulonglong2*)&Wl[j * DD + k * 2];
        wl2[k] = a.x; wl2[k + 1] = a.y;
        ulonglong2 c = *(const ulonglong2*)&Wr[j * DD + k * 2];
        wr2[k] = c.x; wr2[k + 1] = c.y;
    }
    float bj = bl[j];

    int stride = gridDim.x * 8;
    int iA0 = lo + blockIdx.x * 8 + g;
    int iB0 = iA0 + 4;
    float hvA = 0.f, avA = 0.f, hvB = 0.f, avB = 0.f;
    if (iA0 < hi) { hvA = h[iA0 * DD + j]; avA = agg[iA0 * DD + j]; }
    if (iB0 < hi) { hvB = h[iB0 * DD + j]; avB = agg[iB0 * DD + j]; }
    int buf = 0;
    for (int base = lo + blockIdx.x * 8; base < hi; base += stride) {
        int iA = base + g;
        int iB = iA + 4;
        sh[buf][g][j] = hvA;
        sa[buf][g][j] = avA;
        sh[buf][g + 4][j] = hvB;
        sa[buf][g + 4][j] = avB;
        __syncthreads();
        int nA = iA + stride, nB = iB + stride;
        if (nA < hi) { hvA = h[nA * DD + j]; avA = agg[nA * DD + j]; }
        else         { hvA = 0.f; avA = 0.f; }
        if (nB < hi) { hvB = h[nB * DD + j]; avB = agg[nB * DD + j]; }
        else         { hvB = 0.f; avB = 0.f; }

        const ulonglong2* hA = (const ulonglong2*)sh[buf][g];
        const ulonglong2* aA = (const ulonglong2*)sa[buf][g];
        const ulonglong2* hB = (const ulonglong2*)sh[buf][g + 4];
        const ulonglong2* aB = (const ulonglong2*)sa[buf][g + 4];
        u64 accA0 = 0ULL, accA1 = 0ULL, accB0 = 0ULL, accB1 = 0ULL;
#pragma unroll
        for (int k4 = 0; k4 < 16; k4++) {
            ulonglong2 Aa = aA[k4];
            ulonglong2 Ha = hA[k4];
            ulonglong2 Ab = aB[k4];
            ulonglong2 Hb = hB[k4];
            u64 wlo = wl2[2 * k4], whi = wl2[2 * k4 + 1];
            u64 rlo = wr2[2 * k4], rhi = wr2[2 * k4 + 1];
            accA0 = fma2(Aa.x, wlo, accA0);
            accA1 = fma2(Aa.y, whi, accA1);
            accA0 = fma2(Ha.x, rlo, accA0);
            accA1 = fma2(Ha.y, rhi, accA1);
            accB0 = fma2(Ab.x, wlo, accB0);
            accB1 = fma2(Ab.y, whi, accB1);
            accB0 = fma2(Hb.x, rlo, accB0);
            accB1 = fma2(Hb.y, rhi, accB1);
        }
        if (iA < hi) {
            float r = (lo32(accA0) + hi32(accA0)) + (lo32(accA1) + hi32(accA1)) + bj;
            if (do_relu) r = fmaxf(r, 0.f);
            out[iA * DD + j] = r;
        }
        if (iB < hi) {
            float r = (lo32(accB0) + hi32(accB0)) + (lo32(accB1) + hi32(accB1)) + bj;
            if (do_relu) r = fmaxf(r, 0.f);
            out[iB * DD + j] = r;
        }
        buf ^= 1;
        __syncthreads();
    }
}

// ---------------- edge dot product (warp per edge, f32x2 lanes) ----------------
__global__ __launch_bounds__(256) void k_edge(
    const float* __restrict__ h, const int* __restrict__ ea,
    const int* __restrict__ eb, float* __restrict__ out, int E) {
    int w = (blockIdx.x * blockDim.x + threadIdx.x) >> 5;
    int lane = threadIdx.x & 31;
    if (w >= E) return;
    int a = ea[w];
    int b = eb[w];
    ulonglong2 va = ((const ulonglong2*)(h + a * DD))[lane >> 1];
    ulonglong2 vb = ((const ulonglong2*)(h + b * DD))[lane >> 1];
    u64 acc = mul2((lane & 1) ? va.y : va.x, (lane & 1) ? vb.y : vb.x);
    float p = lo32(acc) + hi32(acc);
#pragma unroll
    for (int o = 16; o > 0; o >>= 1) p += __shfl_down_sync(0xffffffffu, p, o);
    if (lane == 0) out[w] = p;
}

// ---------------- launch ----------------
static cudaStream_t s_lin = nullptr;    // lin + chunk-B pipeline stream
static cudaEvent_t  s_ev[8] = {};

extern "C" void kernel_launch(void* const* d_in, const int* in_sizes, int n_in,
                              void* d_out, int out_size) {
    const float* x     = (const float*)d_in[0];
    const int*   ei    = (const int*)d_in[1];
    const int*   eli   = (const int*)d_in[2];
    const float* W_lin = (const float*)d_in[3];
    const float* b_lin = (const float*)d_in[4];
    const float* Wl1   = (const float*)d_in[5];
    const float* bl1   = (const float*)d_in[6];
    const float* Wr1   = (const float*)d_in[7];
    const float* Wl2   = (const float*)d_in[8];
    const float* bl2   = (const float*)d_in[9];
    const float* Wr2   = (const float*)d_in[10];

    int N  = in_sizes[0] / DD;      // 100000
    int E  = in_sizes[1] / 2;       // 1000000
    int EL = in_sizes[2] / 2;       // 200000

    const int* src = ei;            // edge_index[0] = source
    const int* dst = ei + E;        // edge_index[1] = target
    const int* ea  = eli;
    const int* eb  = eli + EL;

    float *h0, *h1, *agg;
    int *deg, *rowptr, *cursor, *col;
    u64 *state;
    cudaGetSymbolAddress((void**)&h0, g_h0);
    cudaGetSymbolAddress((void**)&h1, g_h1);
    cudaGetSymbolAddress((void**)&agg, g_agg);
    cudaGetSymbolAddress((void**)&deg, g_deg);
    cudaGetSymbolAddress((void**)&rowptr, g_rowptr);
    cudaGetSymbolAddress((void**)&cursor, g_cursor);
    cudaGetSymbolAddress((void**)&col, g_col);
    cudaGetSymbolAddress((void**)&state, g_scan_state);

    float* preds = (float*)d_out;

    // One-time stream/event creation (first call is the uncaptured correctness
    // run, so no resource creation happens during graph capture).
    if (s_lin == nullptr) {
        cudaStreamCreateWithFlags(&s_lin, cudaStreamNonBlocking);
        for (int i = 0; i < 8; i++)
            cudaEventCreateWithFlags(&s_ev[i], cudaEventDisableTiming);
    }
    cudaEvent_t evF = s_ev[0], evLIN = s_ev[1];
    cudaEvent_t evAggA1 = s_ev[2], evB1 = s_ev[3];
    cudaEvent_t evAggA2 = s_ev[4], evB2 = s_ev[5];

    int nblk = (N + SCAN_CHUNK - 1) / SCAN_CHUNK;   // 196 <= 256
    int NH = (N + 1) / 2;                            // chunk split

    // Fork: node_lin runs on side stream, overlapped with CSR build.
    cudaEventRecord(evF, 0);
    cudaStreamWaitEvent(s_lin, evF, 0);
    k_lin<<<296, 256, 0, s_lin>>>(x, W_lin, b_lin, h0, N);
    cudaEventRecord(evLIN, s_lin);

    // CSR build on the main (captured) stream.
    cudaMemsetAsync(deg, 0, N * sizeof(int), 0);
    cudaMemsetAsync(state, 0, 256 * sizeof(u64), 0);
    k_hist<<<2048, 256>>>(dst, deg, E);
    k_scan<<<nblk, 256>>>(deg, rowptr, cursor, state, N, nblk);
    k_scatter<<<2048, 256>>>(src, dst, cursor, col, E);

    // Join lin before aggregation.
    cudaStreamWaitEvent(0, evLIN, 0);

    int aggA_blocks = (NH * 16 + 255) / 256;
    int aggB_blocks = ((N - NH) * 16 + 255) / 256;

    // ===== layer 1: skewed chunk pipeline =====
    // main: aggA1 -> gemmA1 ; side: (after aggA1) aggB1 -> gemmB1
    k_agg<<<aggA_blocks, 256>>>(h0, rowptr, col, agg, 0, NH);
    cudaEventRecord(evAggA1, 0);
    cudaStreamWaitEvent(s_lin, evAggA1, 0);
    k_gemm<<<148, 256>>>(h0, agg, Wl1, bl1, Wr1, h1, 0, NH, 1);
    k_agg<<<aggB_blocks, 256, 0, s_lin>>>(h0, rowptr, col, agg, NH, N);
    k_gemm<<<148, 256, 0, s_lin>>>(h0, agg, Wl1, bl1, Wr1, h1, NH, N, 1);
    cudaEventRecord(evB1, s_lin);
    cudaStreamWaitEvent(0, evB1, 0);        // h1 fully ready

    // ===== layer 2: same pipeline, h1 -> h0 =====
    k_agg<<<aggA_blocks, 256>>>(h1, rowptr, col, agg, 0, NH);
    cudaEventRecord(evAggA2, 0);
    cudaStreamWaitEvent(s_lin, evAggA2, 0);
    k_gemm<<<148, 256>>>(h1, agg, Wl2, bl2, Wr2, h0, 0, NH, 0);
    k_agg<<<aggB_blocks, 256, 0, s_lin>>>(h1, rowptr, col, agg, NH, N);
    k_gemm<<<148, 256, 0, s_lin>>>(h1, agg, Wl2, bl2, Wr2, h0, NH, N, 0);
    cudaEventRecord(evB2, s_lin);
    cudaStreamWaitEvent(0, evB2, 0);        // h0 fully ready

    // edge classifier
    int blocks = (EL * 32 + 255) / 256;
    k_edge<<<blocks, 256>>>(h0, ea, eb, preds, EL);
}

// round 10
// speedup vs baseline: 1.1949x; 1.1949x over previous
#include <cuda_runtime.h>
#include <cuda_bf16.h>

#define NN 100000
#define DD 64
#define EMAX 1000000
#define SCAN_CHUNK 512   // blocks = ceil(NN/512) = 196 <= 256

typedef unsigned long long u64;

// ---------------- f32x2 packed math (Blackwell sm_103a) ----------------
__device__ __forceinline__ u64 fma2(u64 a, u64 b, u64 c) {
    u64 d;
    asm("fma.rn.f32x2 %0, %1, %2, %3;" : "=l"(d) : "l"(a), "l"(b), "l"(c));
    return d;
}
__device__ __forceinline__ u64 add2(u64 a, u64 b) {
    u64 d;
    asm("add.rn.f32x2 %0, %1, %2;" : "=l"(d) : "l"(a), "l"(b));
    return d;
}
__device__ __forceinline__ u64 mul2(u64 a, u64 b) {
    u64 d;
    asm("mul.rn.f32x2 %0, %1, %2;" : "=l"(d) : "l"(a), "l"(b));
    return d;
}
__device__ __forceinline__ float lo32(u64 a) { return __uint_as_float((unsigned)a); }
__device__ __forceinline__ float hi32(u64 a) { return __uint_as_float((unsigned)(a >> 32)); }

// ---------------- device scratch (no allocation allowed) ----------------
__device__ float g_h0[NN * DD];
__device__ float g_h1[NN * DD];
__device__ float g_p[NN * DD];
__device__ float g_q[NN * DD];
__device__ int   g_deg[NN];
__device__ int   g_rowptr[NN + 1];
__device__ int   g_cursor[NN];
__device__ int   g_col[EMAX];
__device__ u64   g_scan_state[256];   // memset to 0 each launch

// ---------------- CSR build ----------------
__global__ void k_hist(const int* __restrict__ dst, int* __restrict__ deg, int E) {
    for (int e = blockIdx.x * blockDim.x + threadIdx.x; e < E; e += gridDim.x * blockDim.x)
        atomicAdd(&deg[dst[e]], 1);
}

// single-pass decoupled-lookback exclusive scan: deg -> rowptr/cursor
__global__ void k_scan(const int* __restrict__ deg, int* __restrict__ rowptr,
                       int* __restrict__ cursor, u64* __restrict__ state,
                       int n, int nblk) {
    __shared__ int ps[256];
    __shared__ int s_ex;
    int b = blockIdx.x;
    int t = threadIdx.x;
    int base = b * SCAN_CHUNK + t * 2;
    int d0 = (base < n) ? deg[base] : 0;
    int d1 = (base + 1 < n) ? deg[base + 1] : 0;
    ps[t] = d0 + d1;
    __syncthreads();
    for (int d = 1; d < 256; d <<= 1) {
        int v = (t >= d) ? ps[t - d] : 0;
        __syncthreads();
        ps[t] += v;
        __syncthreads();
    }
    int total = ps[255];

    if (t == 0) {
        if (b == 0) {
            atomicExch(&state[0], ((u64)total << 2) | 2ULL);
            s_ex = 0;
        } else {
            atomicExch(&state[b], ((u64)total << 2) | 1ULL);
            int ex = 0;
            int p = b - 1;
            while (true) {
                u64 s;
                do {
                    s = *(volatile u64*)&state[p];
                } while ((s & 3ULL) == 0ULL);
                int v = (int)(s >> 2);
                ex += v;
                if ((s & 3ULL) == 2ULL) break;
                p--;
            }
            atomicExch(&state[b], ((u64)(ex + total) << 2) | 2ULL);
            s_ex = ex;
        }
    }
    __syncthreads();
    int off = s_ex + ps[t] - (d0 + d1);
    if (base < n)     { rowptr[base] = off;          cursor[base] = off; }
    if (base + 1 < n) { rowptr[base + 1] = off + d0; cursor[base + 1] = off + d0; }
    if (b == nblk - 1 && t == 255) rowptr[n] = s_ex + total;
}

__global__ void k_scatter(const int* __restrict__ src, const int* __restrict__ dst,
                          int* __restrict__ cursor, int* __restrict__ col, int E) {
    for (int e = blockIdx.x * blockDim.x + threadIdx.x; e < E; e += gridDim.x * blockDim.x) {
        int d = dst[e];
        int p = atomicAdd(&cursor[d], 1);
        col[p] = src[e];
    }
}

// ---------------- fused mean-aggregate + combine ----------------
// out[i] = act( mean_{j in N(i)} p[j]  +  q[i] )
__global__ __launch_bounds__(256) void k_aggc(
    const float* __restrict__ p, const float* __restrict__ q,
    const int* __restrict__ rowptr, const int* __restrict__ col,
    float* __restrict__ out, int n, int do_relu) {
    int node = (blockIdx.x * blockDim.x + threadIdx.x) >> 4;
    int l = threadIdx.x & 15;
    if (node >= n) return;
    int s = rowptr[node];
    int e = rowptr[node + 1];
    u64 axy = 0ULL, azw = 0ULL;
    int nn = s;
    for (; nn + 8 <= e; nn += 8) {
        int c0 = col[nn],     c1 = col[nn + 1], c2 = col[nn + 2], c3 = col[nn + 3];
        int c4 = col[nn + 4], c5 = col[nn + 5], c6 = col[nn + 6], c7 = col[nn + 7];
        ulonglong2 v0 = ((const ulonglong2*)(p + c0 * DD))[l];
        ulonglong2 v1 = ((const ulonglong2*)(p + c1 * DD))[l];
        ulonglong2 v2 = ((const ulonglong2*)(p + c2 * DD))[l];
        ulonglong2 v3 = ((const ulonglong2*)(p + c3 * DD))[l];
        ulonglong2 v4 = ((const ulonglong2*)(p + c4 * DD))[l];
        ulonglong2 v5 = ((const ulonglong2*)(p + c5 * DD))[l];
        ulonglong2 v6 = ((const ulonglong2*)(p + c6 * DD))[l];
        ulonglong2 v7 = ((const ulonglong2*)(p + c7 * DD))[l];
        u64 p0 = add2(add2(v0.x, v1.x), add2(v2.x, v3.x));
        u64 p1 = add2(add2(v4.x, v5.x), add2(v6.x, v7.x));
        u64 q0 = add2(add2(v0.y, v1.y), add2(v2.y, v3.y));
        u64 q1 = add2(add2(v4.y, v5.y), add2(v6.y, v7.y));
        axy = add2(axy, add2(p0, p1));
        azw = add2(azw, add2(q0, q1));
    }
    for (; nn + 4 <= e; nn += 4) {
        int c0 = col[nn], c1 = col[nn + 1], c2 = col[nn + 2], c3 = col[nn + 3];
        ulonglong2 v0 = ((const ulonglong2*)(p + c0 * DD))[l];
        ulonglong2 v1 = ((const ulonglong2*)(p + c1 * DD))[l];
        ulonglong2 v2 = ((const ulonglong2*)(p + c2 * DD))[l];
        ulonglong2 v3 = ((const ulonglong2*)(p + c3 * DD))[l];
        axy = add2(axy, add2(add2(v0.x, v1.x), add2(v2.x, v3.x)));
        azw = add2(azw, add2(add2(v0.y, v1.y), add2(v2.y, v3.y)));
    }
    for (; nn < e; nn++) {
        ulonglong2 v = ((const ulonglong2*)(p + col[nn] * DD))[l];
        axy = add2(axy, v.x);
        azw = add2(azw, v.y);
    }
    float inv = (e > s) ? 1.f / (float)(e - s) : 0.f;
    unsigned ui = __float_as_uint(inv);
    u64 inv2 = ((u64)ui << 32) | ui;
    ulonglong2 qv = ((const ulonglong2*)(q + node * DD))[l];
    u64 rxy = add2(mul2(axy, inv2), qv.x);
    u64 rzw = add2(mul2(azw, inv2), qv.y);
    if (do_relu) {
        float x0 = fmaxf(lo32(rxy), 0.f), x1 = fmaxf(hi32(rxy), 0.f);
        float x2 = fmaxf(lo32(rzw), 0.f), x3 = fmaxf(hi32(rzw), 0.f);
        rxy = ((u64)__float_as_uint(x1) << 32) | __float_as_uint(x0);
        rzw = ((u64)__float_as_uint(x3) << 32) | __float_as_uint(x2);
    }
    ((ulonglong2*)(out + node * DD))[l] = make_ulonglong2(rxy, rzw);
}

// ---------------- node linear: out = x @ W^T + b (f32x2, double-buffered) ----------------
__global__ __launch_bounds__(256, 2) void k_lin(
    const float* __restrict__ x, const float* __restrict__ W,
    const float* __restrict__ b, float* __restrict__ out, int n) {
    __shared__ __align__(16) float sh[2][4][DD];
    int tid = threadIdx.x;
    int g = tid >> 6;
    int j = tid & 63;

    u64 w2[32];
#pragma unroll
    for (int k = 0; k < 32; k += 2) {
        ulonglong2 a = *(const ulonglong2*)&W[j * DD + k * 2];
        w2[k] = a.x;
        w2[k + 1] = a.y;
    }
    float bj = b[j];

    int stride = gridDim.x * 4;
    int i0 = blockIdx.x * 4 + g;
    float hv = (i0 < n) ? x[i0 * DD + j] : 0.f;
    int buf = 0;
    for (int base = blockIdx.x * 4; base < n; base += stride) {
        int i = base + g;
        sh[buf][g][j] = hv;
        __syncthreads();
        int inx = i + stride;
        hv = (inx < n) ? x[inx * DD + j] : 0.f;
        if (i < n) {
            const ulonglong2* h2 = (const ulonglong2*)sh[buf][g];
            u64 acc0 = 0ULL, acc1 = 0ULL;
#pragma unroll
            for (int k4 = 0; k4 < 16; k4++) {
                ulonglong2 H = h2[k4];
                acc0 = fma2(H.x, w2[2 * k4], acc0);
                acc1 = fma2(H.y, w2[2 * k4 + 1], acc1);
            }
            out[i * DD + j] = (lo32(acc0) + hi32(acc0)) + (lo32(acc1) + hi32(acc1)) + bj;
        }
        buf ^= 1;
    }
}

// ---------------- dual-output transform: p = h@Wl^T, q = h@Wr^T + bl ----------------
// 8 nodes per block-iteration; each thread computes col j for 2 nodes.
__global__ __launch_bounds__(256, 1) void k_gemmPQ(
    const float* __restrict__ h,
    const float* __restrict__ Wl, const float* __restrict__ Wr,
    const float* __restrict__ bl,
    float* __restrict__ p, float* __restrict__ q, int n) {
    __shared__ __align__(16) float sh[2][8][DD];
    int tid = threadIdx.x;
    int g = tid >> 6;       // 0..3
    int j = tid & 63;

    u64 wl2[32], wr2[32];
#pragma unroll
    for (int k = 0; k < 32; k += 2) {
        ulonglong2 a = *(const ulonglong2*)&Wl[j * DD + k * 2];
        wl2[k] = a.x; wl2[k + 1] = a.y;
        ulonglong2 c = *(const ulonglong2*)&Wr[j * DD + k * 2];
        wr2[k] = c.x; wr2[k + 1] = c.y;
    }
    float bj = bl[j];

    int stride = gridDim.x * 8;
    int iA0 = blockIdx.x * 8 + g;
    int iB0 = iA0 + 4;
    float hvA = (iA0 < n) ? h[iA0 * DD + j] : 0.f;
    float hvB = (iB0 < n) ? h[iB0 * DD + j] : 0.f;
    int buf = 0;
    for (int base = blockIdx.x * 8; base < n; base += stride) {
        int iA = base + g;
        int iB = iA + 4;
        sh[buf][g][j] = hvA;
        sh[buf][g + 4][j] = hvB;
        __syncthreads();
        int nA = iA + stride, nB = iB + stride;
        hvA = (nA < n) ? h[nA * DD + j] : 0.f;
        hvB = (nB < n) ? h[nB * DD + j] : 0.f;

        const ulonglong2* hA = (const ulonglong2*)sh[buf][g];
        const ulonglong2* hB = (const ulonglong2*)sh[buf][g + 4];
        u64 pA0 = 0ULL, pA1 = 0ULL, qA0 = 0ULL, qA1 = 0ULL;
        u64 pB0 = 0ULL, pB1 = 0ULL, qB0 = 0ULL, qB1 = 0ULL;
#pragma unroll
        for (int k4 = 0; k4 < 16; k4++) {
            ulonglong2 Ha = hA[k4];
            ulonglong2 Hb = hB[k4];
            u64 wlo = wl2[2 * k4], whi = wl2[2 * k4 + 1];
            u64 rlo = wr2[2 * k4], rhi = wr2[2 * k4 + 1];
            pA0 = fma2(Ha.x, wlo, pA0);
            pA1 = fma2(Ha.y, whi, pA1);
            qA0 = fma2(Ha.x, rlo, qA0);
            qA1 = fma2(Ha.y, rhi, qA1);
            pB0 = fma2(Hb.x, wlo, pB0);
            pB1 = fma2(Hb.y, whi, pB1);
            qB0 = fma2(Hb.x, rlo, qB0);
            qB1 = fma2(Hb.y, rhi, qB1);
        }
        if (iA < n) {
            p[iA * DD + j] = (lo32(pA0) + hi32(pA0)) + (lo32(pA1) + hi32(pA1));
            q[iA * DD + j] = (lo32(qA0) + hi32(qA0)) + (lo32(qA1) + hi32(qA1)) + bj;
        }
        if (iB < n) {
            p[iB * DD + j] = (lo32(pB0) + hi32(pB0)) + (lo32(pB1) + hi32(pB1));
            q[iB * DD + j] = (lo32(qB0) + hi32(qB0)) + (lo32(qB1) + hi32(qB1)) + bj;
        }
        buf ^= 1;
        __syncthreads();
    }
}

// ---------------- edge dot product (warp per edge, f32x2 lanes) ----------------
__global__ __launch_bounds__(256) void k_edge(
    const float* __restrict__ h, const int* __restrict__ ea,
    const int* __restrict__ eb, float* __restrict__ out, int E) {
    int w = (blockIdx.x * blockDim.x + threadIdx.x) >> 5;
    int lane = threadIdx.x & 31;
    if (w >= E) return;
    int a = ea[w];
    int b = eb[w];
    ulonglong2 va = ((const ulonglong2*)(h + a * DD))[lane >> 1];
    ulonglong2 vb = ((const ulonglong2*)(h + b * DD))[lane >> 1];
    u64 acc = mul2((lane & 1) ? va.y : va.x, (lane & 1) ? vb.y : vb.x);
    float p = lo32(acc) + hi32(acc);
#pragma unroll
    for (int o = 16; o > 0; o >>= 1) p += __shfl_down_sync(0xffffffffu, p, o);
    if (lane == 0) out[w] = p;
}

// ---------------- launch ----------------
static cudaStream_t s_lin = nullptr;
static cudaEvent_t  s_evF = nullptr;
static cudaEvent_t  s_evPQ = nullptr;

extern "C" void kernel_launch(void* const* d_in, const int* in_sizes, int n_in,
                              void* d_out, int out_size) {
    const float* x     = (const float*)d_in[0];
    const int*   ei    = (const int*)d_in[1];
    const int*   eli   = (const int*)d_in[2];
    const float* W_lin = (const float*)d_in[3];
    const float* b_lin = (const float*)d_in[4];
    const float* Wl1   = (const float*)d_in[5];
    const float* bl1   = (const float*)d_in[6];
    const float* Wr1   = (const float*)d_in[7];
    const float* Wl2   = (const float*)d_in[8];
    const float* bl2   = (const float*)d_in[9];
    const float* Wr2   = (const float*)d_in[10];

    int N  = in_sizes[0] / DD;      // 100000
    int E  = in_sizes[1] / 2;       // 1000000
    int EL = in_sizes[2] / 2;       // 200000

    const int* src = ei;            // edge_index[0] = source
    const int* dst = ei + E;        // edge_index[1] = target
    const int* ea  = eli;
    const int* eb  = eli + EL;

    float *h0, *h1, *p, *q;
    int *deg, *rowptr, *cursor, *col;
    u64 *state;
    cudaGetSymbolAddress((void**)&h0, g_h0);
    cudaGetSymbolAddress((void**)&h1, g_h1);
    cudaGetSymbolAddress((void**)&p, g_p);
    cudaGetSymbolAddress((void**)&q, g_q);
    cudaGetSymbolAddress((void**)&deg, g_deg);
    cudaGetSymbolAddress((void**)&rowptr, g_rowptr);
    cudaGetSymbolAddress((void**)&cursor, g_cursor);
    cudaGetSymbolAddress((void**)&col, g_col);
    cudaGetSymbolAddress((void**)&state, g_scan_state);

    float* preds = (float*)d_out;

    // One-time stream/event creation (first call is the uncaptured correctness
    // run, so no resource creation happens during graph capture).
    if (s_lin == nullptr) {
        cudaStreamCreateWithFlags(&s_lin, cudaStreamNonBlocking);
        cudaEventCreateWithFlags(&s_evF, cudaEventDisableTiming);
        cudaEventCreateWithFlags(&s_evPQ, cudaEventDisableTiming);
    }

    int nblk = (N + SCAN_CHUNK - 1) / SCAN_CHUNK;   // 196 <= 256

    // Side stream: node_lin then layer-1 transform (p0,q0) — both independent
    // of the CSR build, fully overlapped with it.
    cudaEventRecord(s_evF, 0);
    cudaStreamWaitEvent(s_lin, s_evF, 0);
    k_lin<<<296, 256, 0, s_lin>>>(x, W_lin, b_lin, h0, N);
    k_gemmPQ<<<148, 256, 0, s_lin>>>(h0, Wl1, Wr1, bl1, p, q, N);
    cudaEventRecord(s_evPQ, s_lin);

    // Main stream: CSR build.
    cudaMemsetAsync(deg, 0, N * sizeof(int), 0);
    cudaMemsetAsync(state, 0, 256 * sizeof(u64), 0);
    k_hist<<<2048, 256>>>(dst, deg, E);
    k_scan<<<nblk, 256>>>(deg, rowptr, cursor, state, N, nblk);
    k_scatter<<<2048, 256>>>(src, dst, cursor, col, E);

    // Join: aggregation needs p,q and CSR.
    cudaStreamWaitEvent(0, s_evPQ, 0);

    int agg_blocks = (N * 16 + 255) / 256;

    // layer 1: h1 = relu(agg(p) + q)
    k_aggc<<<agg_blocks, 256>>>(p, q, rowptr, col, h1, N, 1);
    // layer 2 transform: p,q from h1
    k_gemmPQ<<<148, 256>>>(h1, Wl2, Wr2, bl2, p, q, N);
    // layer 2 combine: h0 = agg(p) + q
    k_aggc<<<agg_blocks, 256>>>(p, q, rowptr, col, h0, N, 0);

    // edge classifier
    int blocks = (EL * 32 + 255) / 256;
    k_edge<<<blocks, 256>>>(h0, ea, eb, preds, EL);
}